// round 15
// baseline (speedup 1.0000x reference)
#include <cuda_runtime.h>

#define BAG 15
#define IM 28
#define POSMAX 20
#define LAM 0.001f
#define TPB 128
#define MAXB 65536
#define MAXW (MAXB * 2 / 32)   /* 4096 warps max (2 threads/sample) */
#define NPMAX 225

__device__ __align__(16) float g_WiT[66 * 16];   // WiT[k*16+u] = Wi[u*66+k], col 15 = 0
__device__ __align__(16) float g_reffT[16 * 16]; // [j*16+u] = Reff[u][j]
__device__ float g_state[BAG * MAXB];            // [u][b]
__device__ unsigned int g_pos[MAXB];             // r | (c<<8)
__device__ float g_partial[NPMAX * MAXW];        // [pair][warp] partial sums (3.7MB)
__device__ int g_pidx[NPMAX];                    // flattened mask index of active pairs
__device__ int g_pij[NPMAX];                     // i | (j<<8)
__device__ int g_np;
__device__ unsigned int g_ctr;                   // last-block counter

__device__ __forceinline__ float warp_sum(float v) {
    v += __shfl_xor_sync(0xffffffffu, v, 16);
    v += __shfl_xor_sync(0xffffffffu, v, 8);
    v += __shfl_xor_sync(0xffffffffu, v, 4);
    v += __shfl_xor_sync(0xffffffffu, v, 2);
    v += __shfl_xor_sync(0xffffffffu, v, 1);
    return v;
}

// acc[0..14] += val * base[0..14]   (base 16B-aligned shared, padded to 16 floats)
#define FMA15S(val, base) do {                                             \
    const float4* _wp = (const float4*)(base);                             \
    float4 _w0 = _wp[0], _w1 = _wp[1], _w2 = _wp[2], _w3 = _wp[3];         \
    float _v = (val);                                                      \
    acc[0]  = fmaf(_v, _w0.x, acc[0]);  acc[1]  = fmaf(_v, _w0.y, acc[1]); \
    acc[2]  = fmaf(_v, _w0.z, acc[2]);  acc[3]  = fmaf(_v, _w0.w, acc[3]); \
    acc[4]  = fmaf(_v, _w1.x, acc[4]);  acc[5]  = fmaf(_v, _w1.y, acc[5]); \
    acc[6]  = fmaf(_v, _w1.z, acc[6]);  acc[7]  = fmaf(_v, _w1.w, acc[7]); \
    acc[8]  = fmaf(_v, _w2.x, acc[8]);  acc[9]  = fmaf(_v, _w2.y, acc[9]); \
    acc[10] = fmaf(_v, _w2.z, acc[10]); acc[11] = fmaf(_v, _w2.w, acc[11]);\
    acc[12] = fmaf(_v, _w3.x, acc[12]); acc[13] = fmaf(_v, _w3.y, acc[13]);\
    acc[14] = fmaf(_v, _w3.z, acc[14]);                                    \
} while (0)

__global__ void prep_kernel(const float* __restrict__ Wi, const float* __restrict__ mask) {
    int t = threadIdx.x;
    for (int idx = t; idx < 66 * 16; idx += 256) {
        int k = idx >> 4, u = idx & 15;
        g_WiT[idx] = (u < 15) ? Wi[u * 66 + k] : 0.0f;
    }
    for (int idx = t; idx < 256; idx += 256) g_reffT[idx] = 0.0f;
    if (t == 0) {
        g_ctr = 0;
        int np = 0;
        for (int idx = 0; idx < 225; idx++) {
            if (mask[idx] != 0.0f) {
                g_pidx[np] = idx;
                g_pij[np] = (idx / 15) | ((idx % 15) << 8);
                np++;
            }
        }
        g_np = np;
    }
}

// 2 threads per sample: half 0 = patch rows 0-3, recurrent j=0-7, bias;
// half 1 = patch rows 4-7, recurrent j=8-14, pos terms. shfl_xor(1) combine.
// MODE 0: first step (pos fixed (10,10), no recurrent) + fused reff.
// MODE 1: middle + fused reff. MODE 2: last (logits only).
template <int MODE>
__global__ __launch_bounds__(TPB, 6) void step_kernel(
    const float* __restrict__ x,
    const float* __restrict__ bi, const float* __restrict__ gamma,
    const float* __restrict__ beta, const float* __restrict__ rb,
    const float* __restrict__ Wc, const float* __restrict__ bc,
    const float* __restrict__ Wo, const float* __restrict__ bo,
    const float* __restrict__ R, const float* __restrict__ mask,
    float* __restrict__ out, int B)
{
    __shared__ __align__(16) float sh_wi[66 * 16];
    __shared__ __align__(16) float sh_rf[16 * 16];
    __shared__ float sh_s[BAG][TPB];
    __shared__ int sh_pp[NPMAX];
    __shared__ unsigned int sh_last;

    int tid = threadIdx.x;
    int gid = blockIdx.x * TPB + tid;
    int half = gid & 1;
    int b = gid >> 1;
    bool on = (b < B);
    int bb = on ? b : 0;

    // issue position + state loads first (one overlapped latency window)
    int r, c;
    if (MODE == 0) { r = 10; c = 10; }
    else { unsigned int p = g_pos[bb]; r = (int)(p & 255u); c = (int)(p >> 8); }
    float st[8];
    int jbase = half ? 8 : 0;
    int jcnt = half ? 7 : 8;
    if (MODE) {
#pragma unroll
        for (int j = 0; j < 8; j++)
            st[j] = (j < jcnt) ? g_state[(jbase + j) * MAXB + bb] : 0.0f;
    }

    // stage weights (and pair list) into shared
    {
        const float4* s = (const float4*)g_WiT;
        float4* d = (float4*)sh_wi;
        for (int i = tid; i < 264; i += TPB) d[i] = s[i];
        if (MODE) {
            const float4* s2 = (const float4*)g_reffT;
            float4* d2 = (float4*)sh_rf;
            if (tid < 64) d2[tid] = s2[tid];
        }
        if (MODE < 2)
            for (int i = tid; i < NPMAX; i += TPB) sh_pp[i] = g_pij[i];
    }
    __syncthreads();

    float acc[15];
#pragma unroll
    for (int u = 0; u < 15; u++)
        acc[u] = half ? 0.0f : (bi[u] + (MODE ? rb[u] : 0.0f));

    if (MODE) {
#pragma unroll
        for (int j = 0; j < 8; j++)
            if (j < jcnt) FMA15S(st[j], sh_rf + (jbase + j) * 16);
        if (half) {
            float pr = (float)r * (2.0f / (float)POSMAX) - 1.0f;
            float pc = (float)c * (2.0f / (float)POSMAX) - 1.0f;
            FMA15S(pr, sh_wi + 64 * 16);
            FMA15S(pc, sh_wi + 65 * 16);
        }
    }
    // MODE 0: pos terms are (10/20*2-1) = 0 -> skip entirely.

    // ---- half's 4 patch rows straight from x: 3 aligned float4 + SEL shift ----
    // r,c in [6,14] always (start (10,10), <=4 unit moves) -> in-bounds.
    {
        int cb = c & ~3;          // in {4,8,12}
        int sh = c & 3;
        const float* img = x + (size_t)bb * (IM * IM) + (size_t)(r + half * 4) * IM + cb;
        bool s2 = (sh & 2) != 0;
        bool s1 = (sh & 1) != 0;
#pragma unroll
        for (int i = 0; i < 4; i++) {
            const float4* rp = (const float4*)(img + i * IM);
            float4 a0 = rp[0];
            float4 a1 = rp[1];
            float4 a2 = rp[2];
            float v0 = a0.x, v1 = a0.y, v2 = a0.z, v3 = a0.w;
            float v4 = a1.x, v5 = a1.y, v6 = a1.z, v7 = a1.w;
            float v8 = a2.x, v9 = a2.y, v10 = a2.z;
            float t0 = s2 ? v2 : v0, t1 = s2 ? v3 : v1, t2 = s2 ? v4 : v2;
            float t3 = s2 ? v5 : v3, t4 = s2 ? v6 : v4, t5 = s2 ? v7 : v5;
            float t6 = s2 ? v8 : v6, t7 = s2 ? v9 : v7, t8 = s2 ? v10 : v8;
            float f0 = s1 ? t1 : t0, f1 = s1 ? t2 : t1, f2 = s1 ? t3 : t2;
            float f3 = s1 ? t4 : t3, f4 = s1 ? t5 : t4, f5 = s1 ? t6 : t5;
            float f6 = s1 ? t7 : t6, f7 = s1 ? t8 : t7;
            int wrow = (half * 4 + i) * 8;
            FMA15S(f0, sh_wi + (wrow + 0) * 16);
            FMA15S(f1, sh_wi + (wrow + 1) * 16);
            FMA15S(f2, sh_wi + (wrow + 2) * 16);
            FMA15S(f3, sh_wi + (wrow + 3) * 16);
            FMA15S(f4, sh_wi + (wrow + 4) * 16);
            FMA15S(f5, sh_wi + (wrow + 5) * 16);
            FMA15S(f6, sh_wi + (wrow + 6) * 16);
            FMA15S(f7, sh_wi + (wrow + 7) * 16);
        }
    }

    // ---- combine halves: both lanes of the pair get the full in_act ----
#pragma unroll
    for (int u = 0; u < 15; u++)
        acc[u] += __shfl_xor_sync(0xffffffffu, acc[u], 1);

    // ---- relu + layernorm (redundant in both halves; trivial ALU) ----
    float mu = 0.0f;
#pragma unroll
    for (int u = 0; u < 15; u++) { acc[u] = fmaxf(acc[u], 0.0f); mu += acc[u]; }
    mu *= (1.0f / 15.0f);
    float var = 0.0f;
#pragma unroll
    for (int u = 0; u < 15; u++) { float d = acc[u] - mu; acc[u] = d; var += d * d; }
    var *= (1.0f / 15.0f);
    float inv = rsqrtf(var + 1e-5f);
    float s[15];
#pragma unroll
    for (int u = 0; u < 15; u++) s[u] = acc[u] * inv * gamma[u] + beta[u];

    if (MODE < 2) {
        // split the state store across the pair
        if (on) {
#pragma unroll
            for (int u = 0; u < 8; u++) {
                int uu = jbase + u;
                if (u < jcnt) g_state[uu * MAXB + b] = s[uu];
            }
        }
        // control head (tanh skipped: odd + strictly monotone, decisions identical)
        float c0 = bc[0], c1 = bc[1];
#pragma unroll
        for (int u = 0; u < 15; u++) {
            c0 = fmaf(s[u], Wc[u], c0);
            c1 = fmaf(s[u], Wc[15 + u], c1);
        }
        bool rsel = fabsf(c0) >= fabsf(c1);
        int mr = rsel ? ((c0 > 0.0f) ? 1 : ((c0 < 0.0f) ? -1 : 0)) : 0;
        int mc = rsel ? 0 : ((c1 > 0.0f) ? 1 : ((c1 < 0.0f) ? -1 : 0));
        int nr = min(max(r + mr, 0), POSMAX);
        int nc = min(max(c + mc, 0), POSMAX);
        if (on && half == 0) g_pos[b] = (unsigned int)nr | ((unsigned int)nc << 8);

        // coact: two pairs per 4-stage parity reduction.
        // Even lanes (half 0) hold the warp's 16 samples for pair p2,
        // odd lanes (half 1) the same 16 samples for pair p2+1.
#pragma unroll
        for (int u = 0; u < 15; u++) sh_s[u][tid] = on ? s[u] : 0.0f;
        int np = g_np;
        int lane = tid & 31;
        int wg = gid >> 5;          // global warp id
        for (int p2 = 0; p2 < np; p2 += 2) {
            int pe = p2 + half;
            float v = 0.0f;
            if (pe < np) {
                int e = sh_pp[pe];
                v = sh_s[e & 255][tid] * sh_s[e >> 8][tid];
            }
            v += __shfl_xor_sync(0xffffffffu, v, 2);
            v += __shfl_xor_sync(0xffffffffu, v, 4);
            v += __shfl_xor_sync(0xffffffffu, v, 8);
            v += __shfl_xor_sync(0xffffffffu, v, 16);
            if (lane < 2 && p2 + lane < np)
                g_partial[(p2 + lane) * MAXW + wg] = v;
        }

        // ---- fused reff: last block reduces partials into g_reffT ----
        __threadfence();
        if (tid == 0)
            sh_last = (atomicAdd(&g_ctr, 1u) == (unsigned)(gridDim.x - 1)) ? 1u : 0u;
        __syncthreads();
        if (sh_last) {
            int NW = gridDim.x * (TPB / 32);
            int n4 = NW >> 2;
            int wid = tid >> 5;
            for (int p = wid; p < np; p += (TPB / 32)) {
                const float4* s4 = (const float4*)(g_partial + p * MAXW);
                float a = 0.0f;
                for (int t = lane; t < n4; t += 32) {
                    float4 v = s4[t];
                    a += (v.x + v.y) + (v.z + v.w);
                }
                a = warp_sum(a);
                if (lane == 0) {
                    int idx = g_pidx[p];
                    int i = idx / 15, j = idx % 15;
                    g_reffT[j * 16 + i] = (R[idx] - LAM * (a / (float)B)) * mask[idx];
                }
            }
            __syncthreads();
            if (tid == 0) g_ctr = 0;
        }
    } else {
        // logits: split the 10 stores across the pair
        if (on) {
#pragma unroll
            for (int k = 0; k < 5; k++) {
                int o2 = half * 5 + k;
                float l = bo[o2];
#pragma unroll
                for (int u = 0; u < 15; u++) l = fmaf(s[u], Wo[o2 * 15 + u], l);
                __stcs(&out[(size_t)b * 10 + o2], l);
            }
        }
    }
}

extern "C" void kernel_launch(void* const* d_in, const int* in_sizes, int n_in,
                              void* d_out, int out_size) {
    const float* x     = (const float*)d_in[0];
    const float* Wi    = (const float*)d_in[1];
    const float* bi    = (const float*)d_in[2];
    const float* gamma = (const float*)d_in[3];
    const float* beta  = (const float*)d_in[4];
    const float* R     = (const float*)d_in[5];
    const float* rb    = (const float*)d_in[6];
    const float* mask  = (const float*)d_in[7];
    const float* Wc    = (const float*)d_in[8];
    const float* bc    = (const float*)d_in[9];
    const float* Wo    = (const float*)d_in[10];
    const float* bo    = (const float*)d_in[11];
    float* out = (float*)d_out;

    int B = in_sizes[0] / (IM * IM);
    if (B > MAXB) B = MAXB;
    int nblk = (2 * B + TPB - 1) / TPB;

    prep_kernel<<<1, 256>>>(Wi, mask);
    step_kernel<0><<<nblk, TPB>>>(x, bi, gamma, beta, rb, Wc, bc, Wo, bo, R, mask, out, B);
    step_kernel<1><<<nblk, TPB>>>(x, bi, gamma, beta, rb, Wc, bc, Wo, bo, R, mask, out, B);
    step_kernel<1><<<nblk, TPB>>>(x, bi, gamma, beta, rb, Wc, bc, Wo, bo, R, mask, out, B);
    step_kernel<1><<<nblk, TPB>>>(x, bi, gamma, beta, rb, Wc, bc, Wo, bo, R, mask, out, B);
    step_kernel<2><<<nblk, TPB>>>(x, bi, gamma, beta, rb, Wc, bc, Wo, bo, R, mask, out, B);
}

// round 16
// speedup vs baseline: 1.4561x; 1.4561x over previous
#include <cuda_runtime.h>

#define BAG 15
#define IM 28
#define POSMAX 20
#define LAM 0.001f
#define TPB 128
#define MAXB 65536
#define MAXW (MAXB / 32)   /* 2048 warps */
#define NPMAX 225
#define NSTEP 5

__device__ __align__(16) float g_WiT[66 * 16];   // WiT[k*16+u] = Wi[u*66+k], col 15 = 0
__device__ __align__(16) float g_reffT[16 * 16]; // [j*16+u] = Reff[u][j]
__device__ float g_partial[NPMAX * MAXW];        // [pair][warp] partial sums
__device__ int g_pidx[NPMAX];                    // flattened mask index of active pairs
__device__ int g_pij[NPMAX];                     // i | (j<<8)
__device__ int g_np;
__device__ unsigned int g_ctr;                   // barrier counter
__device__ volatile unsigned int g_sense;        // barrier phase (release)

__device__ __forceinline__ float warp_sum(float v) {
    v += __shfl_xor_sync(0xffffffffu, v, 16);
    v += __shfl_xor_sync(0xffffffffu, v, 8);
    v += __shfl_xor_sync(0xffffffffu, v, 4);
    v += __shfl_xor_sync(0xffffffffu, v, 2);
    v += __shfl_xor_sync(0xffffffffu, v, 1);
    return v;
}

// acc[0..14] += val * base[0..14]   (base 16B-aligned shared, padded to 16 floats)
#define FMA15S(val, base) do {                                             \
    const float4* _wp = (const float4*)(base);                             \
    float4 _w0 = _wp[0], _w1 = _wp[1], _w2 = _wp[2], _w3 = _wp[3];         \
    float _v = (val);                                                      \
    acc[0]  = fmaf(_v, _w0.x, acc[0]);  acc[1]  = fmaf(_v, _w0.y, acc[1]); \
    acc[2]  = fmaf(_v, _w0.z, acc[2]);  acc[3]  = fmaf(_v, _w0.w, acc[3]); \
    acc[4]  = fmaf(_v, _w1.x, acc[4]);  acc[5]  = fmaf(_v, _w1.y, acc[5]); \
    acc[6]  = fmaf(_v, _w1.z, acc[6]);  acc[7]  = fmaf(_v, _w1.w, acc[7]); \
    acc[8]  = fmaf(_v, _w2.x, acc[8]);  acc[9]  = fmaf(_v, _w2.y, acc[9]); \
    acc[10] = fmaf(_v, _w2.z, acc[10]); acc[11] = fmaf(_v, _w2.w, acc[11]);\
    acc[12] = fmaf(_v, _w3.x, acc[12]); acc[13] = fmaf(_v, _w3.y, acc[13]);\
    acc[14] = fmaf(_v, _w3.z, acc[14]);                                    \
} while (0)

__global__ void prep_kernel(const float* __restrict__ Wi, const float* __restrict__ mask) {
    int t = threadIdx.x;
    for (int idx = t; idx < 66 * 16; idx += 256) {
        int k = idx >> 4, u = idx & 15;
        g_WiT[idx] = (u < 15) ? Wi[u * 66 + k] : 0.0f;
    }
    for (int idx = t; idx < 256; idx += 256) g_reffT[idx] = 0.0f;
    if (t == 0) {
        g_ctr = 0;
        g_sense = 0;
        int np = 0;
        for (int idx = 0; idx < 225; idx++) {
            if (mask[idx] != 0.0f) {
                g_pidx[np] = idx;
                g_pij[np] = (idx / 15) | ((idx % 15) << 8);
                np++;
            }
        }
        g_np = np;
    }
}

// Persistent kernel: all 5 steps in one launch. State + position live in
// registers; device-wide sense-reversing barrier between steps; last-arriving
// block reduces coact partials into g_reffT (fixed tree -> deterministic).
// Grid (512 blocks @ __launch_bounds__(128,4)) is fully co-resident on 148 SMs.
__global__ __launch_bounds__(TPB, 4) void cyc_kernel(
    const float* __restrict__ x,
    const float* __restrict__ bi, const float* __restrict__ gamma,
    const float* __restrict__ beta, const float* __restrict__ rb,
    const float* __restrict__ Wc, const float* __restrict__ bc,
    const float* __restrict__ Wo, const float* __restrict__ bo,
    const float* __restrict__ R, const float* __restrict__ mask,
    float* __restrict__ out, int B)
{
    __shared__ __align__(16) float sh_wi[66 * 16];
    __shared__ __align__(16) float sh_rf[16 * 16];
    __shared__ float sh_s[BAG][TPB];
    __shared__ int sh_pp[NPMAX];
    __shared__ unsigned int sh_last;

    int tid = threadIdx.x;
    int b = blockIdx.x * TPB + tid;
    bool on = (b < B);
    int bb = on ? b : 0;

    // stage weights + pair list into shared (once)
    {
        const float4* sw = (const float4*)g_WiT;
        float4* dw = (float4*)sh_wi;
        for (int i = tid; i < 264; i += TPB) dw[i] = sw[i];
        for (int i = tid; i < NPMAX; i += TPB) sh_pp[i] = g_pij[i];
    }
    __syncthreads();

    int r = 10, c = 10;
    float s[15];
    const float* img0 = x + (size_t)bb * (IM * IM);
    int np = g_np;
    int lane = tid & 31;
    int wg = b >> 5;

#pragma unroll 1
    for (int step = 0; step < NSTEP; step++) {
        float acc[15];
#pragma unroll
        for (int u = 0; u < 15; u++) acc[u] = bi[u] + (step ? rb[u] : 0.0f);

        if (step) {
#pragma unroll
            for (int j = 0; j < 15; j++) FMA15S(s[j], sh_rf + j * 16);
            float pr = (float)r * (2.0f / (float)POSMAX) - 1.0f;
            float pc = (float)c * (2.0f / (float)POSMAX) - 1.0f;
            FMA15S(pr, sh_wi + 64 * 16);
            FMA15S(pc, sh_wi + 65 * 16);
        }
        // step 0: pos terms are 0 -> skipped.

        // ---- 8x8 patch: 3 aligned float4 per row + SEL shift (proven R14) ----
        // r,c in [6,14] always -> in-bounds.
        {
            int cb = c & ~3;
            int sh = c & 3;
            const float* img = img0 + cb;
            bool s2 = (sh & 2) != 0;
            bool s1 = (sh & 1) != 0;
#pragma unroll
            for (int i = 0; i < 8; i++) {
                const float4* rp = (const float4*)(img + (r + i) * IM);
                float4 a0 = rp[0];
                float4 a1 = rp[1];
                float4 a2 = rp[2];
                float v0 = a0.x, v1 = a0.y, v2 = a0.z, v3 = a0.w;
                float v4 = a1.x, v5 = a1.y, v6 = a1.z, v7 = a1.w;
                float v8 = a2.x, v9 = a2.y, v10 = a2.z;
                float t0 = s2 ? v2 : v0, t1 = s2 ? v3 : v1, t2 = s2 ? v4 : v2;
                float t3 = s2 ? v5 : v3, t4 = s2 ? v6 : v4, t5 = s2 ? v7 : v5;
                float t6 = s2 ? v8 : v6, t7 = s2 ? v9 : v7, t8 = s2 ? v10 : v8;
                float f0 = s1 ? t1 : t0, f1 = s1 ? t2 : t1, f2 = s1 ? t3 : t2;
                float f3 = s1 ? t4 : t3, f4 = s1 ? t5 : t4, f5 = s1 ? t6 : t5;
                float f6 = s1 ? t7 : t6, f7 = s1 ? t8 : t7;
                FMA15S(f0, sh_wi + (i * 8 + 0) * 16);
                FMA15S(f1, sh_wi + (i * 8 + 1) * 16);
                FMA15S(f2, sh_wi + (i * 8 + 2) * 16);
                FMA15S(f3, sh_wi + (i * 8 + 3) * 16);
                FMA15S(f4, sh_wi + (i * 8 + 4) * 16);
                FMA15S(f5, sh_wi + (i * 8 + 5) * 16);
                FMA15S(f6, sh_wi + (i * 8 + 6) * 16);
                FMA15S(f7, sh_wi + (i * 8 + 7) * 16);
            }
        }

        // ---- relu + layernorm ----
        float mu = 0.0f;
#pragma unroll
        for (int u = 0; u < 15; u++) { acc[u] = fmaxf(acc[u], 0.0f); mu += acc[u]; }
        mu *= (1.0f / 15.0f);
        float var = 0.0f;
#pragma unroll
        for (int u = 0; u < 15; u++) { float d = acc[u] - mu; acc[u] = d; var += d * d; }
        var *= (1.0f / 15.0f);
        float inv = rsqrtf(var + 1e-5f);
#pragma unroll
        for (int u = 0; u < 15; u++) s[u] = acc[u] * inv * gamma[u] + beta[u];

        if (step < NSTEP - 1) {
            // control head (tanh skipped: odd + strictly monotone)
            float c0 = bc[0], c1 = bc[1];
#pragma unroll
            for (int u = 0; u < 15; u++) {
                c0 = fmaf(s[u], Wc[u], c0);
                c1 = fmaf(s[u], Wc[15 + u], c1);
            }
            bool rsel = fabsf(c0) >= fabsf(c1);
            int mr = rsel ? ((c0 > 0.0f) ? 1 : ((c0 < 0.0f) ? -1 : 0)) : 0;
            int mc = rsel ? 0 : ((c1 > 0.0f) ? 1 : ((c1 < 0.0f) ? -1 : 0));
            r = min(max(r + mr, 0), POSMAX);
            c = min(max(c + mc, 0), POSMAX);

            // coact: per-warp partials (same-thread shared use only)
#pragma unroll
            for (int u = 0; u < 15; u++) sh_s[u][tid] = on ? s[u] : 0.0f;
            for (int p = 0; p < np; p++) {
                int e = sh_pp[p];
                float v = sh_s[e & 255][tid] * sh_s[e >> 8][tid];
                v = warp_sum(v);
                if (lane == 0) g_partial[p * MAXW + wg] = v;
            }

            // ---- device-wide barrier; last block computes g_reffT ----
            unsigned int phase = (unsigned int)(step + 1);
            __threadfence();
            if (tid == 0)
                sh_last = (atomicAdd(&g_ctr, 1u) == (unsigned)(gridDim.x - 1)) ? 1u : 0u;
            __syncthreads();
            if (sh_last) {
                int NW = gridDim.x * (TPB / 32);
                int n4 = NW >> 2;
                int wid = tid >> 5;
                for (int p = wid; p < np; p += (TPB / 32)) {
                    const float4* s4 = (const float4*)(g_partial + p * MAXW);
                    float a = 0.0f;
                    for (int t = lane; t < n4; t += 32) {
                        float4 v = s4[t];
                        a += (v.x + v.y) + (v.z + v.w);
                    }
                    a = warp_sum(a);
                    if (lane == 0) {
                        int idx = g_pidx[p];
                        int i = idx / 15, j = idx % 15;
                        g_reffT[j * 16 + i] = (R[idx] - LAM * (a / (float)B)) * mask[idx];
                    }
                }
                __syncthreads();
                if (tid == 0) {
                    g_ctr = 0;
                    __threadfence();
                    g_sense = phase;   // release
                }
                __syncthreads();
            } else {
                if (tid == 0) {
                    while (g_sense < phase) __nanosleep(64);
                }
                __syncthreads();
                __threadfence();       // acquire
            }
            // refresh sh_rf for next step
            if (tid < 64)
                ((float4*)sh_rf)[tid] = ((const float4*)g_reffT)[tid];
            __syncthreads();
        } else {
            // final step: logits
            if (on) {
#pragma unroll
                for (int o2 = 0; o2 < 10; o2++) {
                    float l = bo[o2];
#pragma unroll
                    for (int u = 0; u < 15; u++) l = fmaf(s[u], Wo[o2 * 15 + u], l);
                    __stcs(&out[(size_t)b * 10 + o2], l);
                }
            }
        }
    }
}

extern "C" void kernel_launch(void* const* d_in, const int* in_sizes, int n_in,
                              void* d_out, int out_size) {
    const float* x     = (const float*)d_in[0];
    const float* Wi    = (const float*)d_in[1];
    const float* bi    = (const float*)d_in[2];
    const float* gamma = (const float*)d_in[3];
    const float* beta  = (const float*)d_in[4];
    const float* R     = (const float*)d_in[5];
    const float* rb    = (const float*)d_in[6];
    const float* mask  = (const float*)d_in[7];
    const float* Wc    = (const float*)d_in[8];
    const float* bc    = (const float*)d_in[9];
    const float* Wo    = (const float*)d_in[10];
    const float* bo    = (const float*)d_in[11];
    float* out = (float*)d_out;

    int B = in_sizes[0] / (IM * IM);
    if (B > MAXB) B = MAXB;
    int nblk = (B + TPB - 1) / TPB;   // 512 for B=65536; co-resident at 4/SM

    prep_kernel<<<1, 256>>>(Wi, mask);
    cyc_kernel<<<nblk, TPB>>>(x, bi, gamma, beta, rb, Wc, bc, Wo, bo, R, mask, out, B);
}

// round 17
// speedup vs baseline: 1.4745x; 1.0127x over previous
#include <cuda_runtime.h>

#define BAG 15
#define IM 28
#define POSMAX 20
#define LAM 0.001f
#define TPB 128
#define MAXB 65536
#define MAXW (MAXB / 32)   /* 2048 warps */
#define NPMAX 225
#define NSTEP 5

__device__ __align__(16) float g_WiT[66 * 16];   // WiT[k*16+u] = Wi[u*66+k], col 15 = 0
__device__ __align__(16) float g_reffT[16 * 16]; // [j*16+u] = Reff[u][j], col 15 = 0
__device__ float g_partial[NPMAX * MAXW];        // [pair][warp] partial sums
__device__ int g_pidx[NPMAX];                    // flattened mask index of active pairs
__device__ int g_pij[NPMAX];                     // i | (j<<8)
__device__ int g_np;
__device__ unsigned int g_ctr;                   // barrier counter
__device__ volatile unsigned int g_sense;        // barrier phase (release)

typedef unsigned long long u64;

__device__ __forceinline__ float warp_sum(float v) {
    v += __shfl_xor_sync(0xffffffffu, v, 16);
    v += __shfl_xor_sync(0xffffffffu, v, 8);
    v += __shfl_xor_sync(0xffffffffu, v, 4);
    v += __shfl_xor_sync(0xffffffffu, v, 2);
    v += __shfl_xor_sync(0xffffffffu, v, 1);
    return v;
}

// packed f32x2 fma: d = a*b + d (per 32-bit lane)
#define FMA2(d, a, b) \
    asm("fma.rn.f32x2 %0, %1, %2, %0;" : "+l"(d) : "l"(a), "l"(b))

// broadcast float into both halves of an f32x2
#define BCAST2(dst, v) \
    asm("mov.b64 %0, {%1, %1};" : "=l"(dst) : "r"(__float_as_uint(v)))

#define UNPACK2(lo, hi, in) \
    asm("mov.b64 {%0, %1}, %2;" : "=f"(lo), "=f"(hi) : "l"(in))

#define PACK2(dst, lo, hi) \
    asm("mov.b64 %0, {%1, %2};" : "=l"(dst) : "f"(lo), "f"(hi))

// acc2[0..7] (8 packed f32x2 = 16 lanes, lane 15 = zero pad) += val * base[0..15]
#define FMA15P(val, base) do {                                             \
    const ulonglong2* _wp = (const ulonglong2*)(base);                     \
    ulonglong2 _a = _wp[0], _b = _wp[1], _c = _wp[2], _d = _wp[3];         \
    u64 _vv; BCAST2(_vv, (val));                                           \
    FMA2(acc2[0], _vv, _a.x); FMA2(acc2[1], _vv, _a.y);                    \
    FMA2(acc2[2], _vv, _b.x); FMA2(acc2[3], _vv, _b.y);                    \
    FMA2(acc2[4], _vv, _c.x); FMA2(acc2[5], _vv, _c.y);                    \
    FMA2(acc2[6], _vv, _d.x); FMA2(acc2[7], _vv, _d.y);                    \
} while (0)

__global__ void prep_kernel(const float* __restrict__ Wi, const float* __restrict__ mask) {
    int t = threadIdx.x;
    for (int idx = t; idx < 66 * 16; idx += 256) {
        int k = idx >> 4, u = idx & 15;
        g_WiT[idx] = (u < 15) ? Wi[u * 66 + k] : 0.0f;
    }
    for (int idx = t; idx < 256; idx += 256) g_reffT[idx] = 0.0f;
    if (t == 0) {
        g_ctr = 0;
        g_sense = 0;
        int np = 0;
        for (int idx = 0; idx < 225; idx++) {
            if (mask[idx] != 0.0f) {
                g_pidx[np] = idx;
                g_pij[np] = (idx / 15) | ((idx % 15) << 8);
                np++;
            }
        }
        g_np = np;
    }
}

// Persistent kernel (R16-verified structure) with packed f32x2 accumulators.
__global__ __launch_bounds__(TPB, 4) void cyc_kernel(
    const float* __restrict__ x,
    const float* __restrict__ bi, const float* __restrict__ gamma,
    const float* __restrict__ beta, const float* __restrict__ rb,
    const float* __restrict__ Wc, const float* __restrict__ bc,
    const float* __restrict__ Wo, const float* __restrict__ bo,
    const float* __restrict__ R, const float* __restrict__ mask,
    float* __restrict__ out, int B)
{
    __shared__ __align__(16) float sh_wi[66 * 16];
    __shared__ __align__(16) float sh_rf[16 * 16];
    __shared__ float sh_s[BAG][TPB];
    __shared__ int sh_pp[NPMAX];
    __shared__ unsigned int sh_last;

    int tid = threadIdx.x;
    int b = blockIdx.x * TPB + tid;
    bool on = (b < B);
    int bb = on ? b : 0;

    // stage weights + pair list into shared (once)
    {
        const float4* sw = (const float4*)g_WiT;
        float4* dw = (float4*)sh_wi;
        for (int i = tid; i < 264; i += TPB) dw[i] = sw[i];
        for (int i = tid; i < NPMAX; i += TPB) sh_pp[i] = g_pij[i];
    }
    __syncthreads();

    int r = 10, c = 10;
    float s[15];
    const float* img0 = x + (size_t)bb * (IM * IM);
    int np = g_np;
    int lane = tid & 31;
    int wg = b >> 5;

#pragma unroll 1
    for (int step = 0; step < NSTEP; step++) {
        u64 acc2[8];
        {
            float b0[16];
#pragma unroll
            for (int u = 0; u < 15; u++) b0[u] = bi[u] + (step ? rb[u] : 0.0f);
            b0[15] = 0.0f;
#pragma unroll
            for (int q = 0; q < 8; q++) PACK2(acc2[q], b0[2 * q], b0[2 * q + 1]);
        }

        if (step) {
#pragma unroll
            for (int j = 0; j < 15; j++) FMA15P(s[j], sh_rf + j * 16);
            float pr = (float)r * (2.0f / (float)POSMAX) - 1.0f;
            float pc = (float)c * (2.0f / (float)POSMAX) - 1.0f;
            FMA15P(pr, sh_wi + 64 * 16);
            FMA15P(pc, sh_wi + 65 * 16);
        }
        // step 0: pos terms are 0 -> skipped.

        // ---- 8x8 patch: 3 aligned float4 per row + SEL shift (proven) ----
        // r,c in [6,14] always -> in-bounds.
        {
            int cb = c & ~3;
            int sh = c & 3;
            const float* img = img0 + cb;
            bool sel2 = (sh & 2) != 0;
            bool sel1 = (sh & 1) != 0;
#pragma unroll
            for (int i = 0; i < 8; i++) {
                const float4* rp = (const float4*)(img + (r + i) * IM);
                float4 a0 = rp[0];
                float4 a1 = rp[1];
                float4 a2 = rp[2];
                float v0 = a0.x, v1 = a0.y, v2 = a0.z, v3 = a0.w;
                float v4 = a1.x, v5 = a1.y, v6 = a1.z, v7 = a1.w;
                float v8 = a2.x, v9 = a2.y, v10 = a2.z;
                float t0 = sel2 ? v2 : v0, t1 = sel2 ? v3 : v1, t2 = sel2 ? v4 : v2;
                float t3 = sel2 ? v5 : v3, t4 = sel2 ? v6 : v4, t5 = sel2 ? v7 : v5;
                float t6 = sel2 ? v8 : v6, t7 = sel2 ? v9 : v7, t8 = sel2 ? v10 : v8;
                float f0 = sel1 ? t1 : t0, f1 = sel1 ? t2 : t1, f2 = sel1 ? t3 : t2;
                float f3 = sel1 ? t4 : t3, f4 = sel1 ? t5 : t4, f5 = sel1 ? t6 : t5;
                float f6 = sel1 ? t7 : t6, f7 = sel1 ? t8 : t7;
                FMA15P(f0, sh_wi + (i * 8 + 0) * 16);
                FMA15P(f1, sh_wi + (i * 8 + 1) * 16);
                FMA15P(f2, sh_wi + (i * 8 + 2) * 16);
                FMA15P(f3, sh_wi + (i * 8 + 3) * 16);
                FMA15P(f4, sh_wi + (i * 8 + 4) * 16);
                FMA15P(f5, sh_wi + (i * 8 + 5) * 16);
                FMA15P(f6, sh_wi + (i * 8 + 6) * 16);
                FMA15P(f7, sh_wi + (i * 8 + 7) * 16);
            }
        }

        // ---- unpack + relu + layernorm ----
        float acc[15];
#pragma unroll
        for (int q = 0; q < 7; q++) UNPACK2(acc[2 * q], acc[2 * q + 1], acc2[q]);
        {
            float hi_dummy;
            UNPACK2(acc[14], hi_dummy, acc2[7]);
            (void)hi_dummy;
        }
        float mu = 0.0f;
#pragma unroll
        for (int u = 0; u < 15; u++) { acc[u] = fmaxf(acc[u], 0.0f); mu += acc[u]; }
        mu *= (1.0f / 15.0f);
        float var = 0.0f;
#pragma unroll
        for (int u = 0; u < 15; u++) { float d = acc[u] - mu; acc[u] = d; var += d * d; }
        var *= (1.0f / 15.0f);
        float inv = rsqrtf(var + 1e-5f);
#pragma unroll
        for (int u = 0; u < 15; u++) s[u] = acc[u] * inv * gamma[u] + beta[u];

        if (step < NSTEP - 1) {
            // control head (tanh skipped: odd + strictly monotone)
            float c0 = bc[0], c1 = bc[1];
#pragma unroll
            for (int u = 0; u < 15; u++) {
                c0 = fmaf(s[u], Wc[u], c0);
                c1 = fmaf(s[u], Wc[15 + u], c1);
            }
            bool rsel = fabsf(c0) >= fabsf(c1);
            int mr = rsel ? ((c0 > 0.0f) ? 1 : ((c0 < 0.0f) ? -1 : 0)) : 0;
            int mc = rsel ? 0 : ((c1 > 0.0f) ? 1 : ((c1 < 0.0f) ? -1 : 0));
            r = min(max(r + mr, 0), POSMAX);
            c = min(max(c + mc, 0), POSMAX);

            // coact: per-warp partials (same-thread shared use only)
#pragma unroll
            for (int u = 0; u < 15; u++) sh_s[u][tid] = on ? s[u] : 0.0f;
            for (int p = 0; p < np; p++) {
                int e = sh_pp[p];
                float v = sh_s[e & 255][tid] * sh_s[e >> 8][tid];
                v = warp_sum(v);
                if (lane == 0) g_partial[p * MAXW + wg] = v;
            }

            // ---- device-wide barrier; last block computes g_reffT ----
            unsigned int phase = (unsigned int)(step + 1);
            __threadfence();
            if (tid == 0)
                sh_last = (atomicAdd(&g_ctr, 1u) == (unsigned)(gridDim.x - 1)) ? 1u : 0u;
            __syncthreads();
            if (sh_last) {
                int NW = gridDim.x * (TPB / 32);
                int n4 = NW >> 2;
                int wid = tid >> 5;
                for (int p = wid; p < np; p += (TPB / 32)) {
                    const float4* s4 = (const float4*)(g_partial + p * MAXW);
                    float a = 0.0f;
                    for (int t = lane; t < n4; t += 32) {
                        float4 v = s4[t];
                        a += (v.x + v.y) + (v.z + v.w);
                    }
                    a = warp_sum(a);
                    if (lane == 0) {
                        int idx = g_pidx[p];
                        int i = idx / 15, j = idx % 15;
                        g_reffT[j * 16 + i] = (R[idx] - LAM * (a / (float)B)) * mask[idx];
                    }
                }
                __syncthreads();
                if (tid == 0) {
                    g_ctr = 0;
                    __threadfence();
                    g_sense = phase;   // release
                }
                __syncthreads();
            } else {
                if (tid == 0) {
                    while (g_sense < phase) __nanosleep(64);
                }
                __syncthreads();
                __threadfence();       // acquire
            }
            // refresh sh_rf for next step
            if (tid < 64)
                ((float4*)sh_rf)[tid] = ((const float4*)g_reffT)[tid];
            __syncthreads();
        } else {
            // final step: logits
            if (on) {
#pragma unroll
                for (int o2 = 0; o2 < 10; o2++) {
                    float l = bo[o2];
#pragma unroll
                    for (int u = 0; u < 15; u++) l = fmaf(s[u], Wo[o2 * 15 + u], l);
                    __stcs(&out[(size_t)b * 10 + o2], l);
                }
            }
        }
    }
}

extern "C" void kernel_launch(void* const* d_in, const int* in_sizes, int n_in,
                              void* d_out, int out_size) {
    const float* x     = (const float*)d_in[0];
    const float* Wi    = (const float*)d_in[1];
    const float* bi    = (const float*)d_in[2];
    const float* gamma = (const float*)d_in[3];
    const float* beta  = (const float*)d_in[4];
    const float* R     = (const float*)d_in[5];
    const float* rb    = (const float*)d_in[6];
    const float* mask  = (const float*)d_in[7];
    const float* Wc    = (const float*)d_in[8];
    const float* bc    = (const float*)d_in[9];
    const float* Wo    = (const float*)d_in[10];
    const float* bo    = (const float*)d_in[11];
    float* out = (float*)d_out;

    int B = in_sizes[0] / (IM * IM);
    if (B > MAXB) B = MAXB;
    int nblk = (B + TPB - 1) / TPB;   // 512 for B=65536; co-resident at 4/SM

    prep_kernel<<<1, 256>>>(Wi, mask);
    cyc_kernel<<<nblk, TPB>>>(x, bi, gamma, beta, rb, Wc, bc, Wo, bo, R, mask, out, B);
}